// round 14
// baseline (speedup 1.0000x reference)
#include <cuda_runtime.h>
#include <cuda_fp16.h>
#include <math_constants.h>

#define N_ENT   100000
#define N_USR   50000
#define N_EDGE  1000000
#define C       64
#define N_FACT  4
#define N_RELM1 9
#define TEMPR   0.2f
// 1 / (2*sqrt(32))
#define INV_SCALE 0.08838834764831845f

#define SCAN_B  1024
#define NB_E    ((N_ENT + SCAN_B - 1) / SCAN_B)   // 98
#define NB_U    ((N_USR + SCAN_B - 1) / SCAN_B)   // 49
#define SBK     ((N_ENT + SCAN_B - 1) / SCAN_B)   // 98 score blocks (1024 ent each)

#define KGB     (N_ENT * 32 / 256)                // 12500 blocks (exact)
#define UIB     (N_USR * 32 / 256)                // 6250 blocks (exact)
#define EB      ((N_EDGE + 255) / 256)            // 3907 edge blocks
#define HB      (N_ENT * C / 4 / 256)             // 6250 fp16-staging blocks

typedef unsigned long long u64;

// ---------------- scratch (device globals; no allocation) ----------------
__device__ __align__(16) float g_V[N_RELM1 * C];     // W W^T w^T, pre-scaled
__device__ float g_wn2[N_RELM1];
__device__ __align__(16) float g_dw[N_FACT * C];     // softmax(att) @ weight
__device__ __align__(16) float g_Sme[N_ENT * 12];    // exp(E·V_r), padded to 12
__device__ __align__(8) __half g_entH[N_ENT * C];    // fp16 copy of entity_emb
__device__ __align__(8) __half g_entAH[N_ENT * C];   // fp16 ent after hop0 norm
__device__ __align__(16) float g_usrA[N_USR * C];    // usr after hop0 norm (fp32)
__device__ u64 g_histE[N_ENT];                       // packed per-head type histogram
__device__ int g_cntE[N_ENT], g_curE[N_ENT];
__device__ int g_cntU[N_USR], g_curU[N_USR];
__device__ int g_offE[N_ENT + 1];
__device__ int g_offU[N_USR + 1];
__device__ __align__(8) int2 g_pkm[N_EDGE];          // .x = tail|type<<20, .y = e2 bits
__device__ __align__(8) int2 g_uiP[N_EDGE];          // CSR-ordered (col, val bits)
__device__ int g_bsumE[128], g_brdyE[128];
__device__ int g_bsumU[128], g_brdyU[128];

// ---------------- packed f32x2 helpers (sm_103a FFMA2 path) ----------------
__device__ __forceinline__ u64 f2mul(u64 x, u64 y) {
    u64 d; asm("mul.rn.f32x2 %0,%1,%2;" : "=l"(d) : "l"(x), "l"(y)); return d;
}
__device__ __forceinline__ u64 f2fma(u64 x, u64 y, u64 c) {
    u64 d; asm("fma.rn.f32x2 %0,%1,%2,%3;" : "=l"(d) : "l"(x), "l"(y), "l"(c)); return d;
}
__device__ __forceinline__ u64 f2bcast(float v) {
    u64 d; asm("mov.b64 %0,{%1,%1};" : "=l"(d) : "f"(v)); return d;
}
__device__ __forceinline__ float2 f2up(u64 v) {
    float2 f; asm("mov.b64 {%0,%1},%2;" : "=f"(f.x), "=f"(f.y) : "l"(v)); return f;
}
__device__ __forceinline__ float p2dot(ulonglong2 a, ulonglong2 b) {
    u64 d = f2mul(a.x, b.x);
    d = f2fma(a.y, b.y, d);
    float2 f = f2up(d);
    return f.x + f.y;
}
// half2 bits -> packed f32x2 (u64)
__device__ __forceinline__ u64 h2f2(unsigned h) {
    __half2 hh = *reinterpret_cast<__half2*>(&h);
    float2 f = __half22float2(hh);
    u64 d; asm("mov.b64 %0,{%1,%2};" : "=l"(d) : "f"(f.x), "f"(f.y));
    return d;
}
__device__ __forceinline__ unsigned h2bits(__half2 h) {
    return *reinterpret_cast<unsigned*>(&h);
}

// ---------------- prep body (runs as extra block of count) ----------------
__device__ void prep_body(const float* __restrict__ weight,
                          const float* __restrict__ kgW,
                          const float* __restrict__ att,
                          float* __restrict__ out_cor,
                          float* sW, float* sWk) {
    int t = threadIdx.x;
    int nt = blockDim.x;
    for (int i = t; i < C * C; i += nt) sW[i] = kgW[i];
    __syncthreads();
    for (int i = t; i < N_RELM1 * C; i += nt) {
        int r = i / C, k = i % C;
        float s = 0.f;
        for (int c = 0; c < C; c++) s += weight[r * C + c] * sW[c * C + k];
        sWk[i] = s;
    }
    __syncthreads();
    for (int i = t; i < N_RELM1 * C; i += nt) {
        int r = i / C, c = i % C;
        float s = 0.f;
        for (int k = 0; k < C; k++) s += sW[c * C + k] * sWk[r * C + k];
        g_V[i] = s * INV_SCALE;
    }
    if (t < N_RELM1) {
        float s = 0.f;
        for (int c = 0; c < C; c++) { float w = weight[t * C + c]; s += w * w; }
        g_wn2[t] = s;
    }
    if (t >= 32 && t < 32 + N_FACT) {
        int f = t - 32;
        float a[N_RELM1]; float m = -CUDART_INF_F;
        for (int j = 0; j < N_RELM1; j++) { a[j] = att[f * N_RELM1 + j]; m = fmaxf(m, a[j]); }
        float ssum = 0.f;
        for (int j = 0; j < N_RELM1; j++) { a[j] = expf(a[j] - m); ssum += a[j]; }
        for (int j = 0; j < N_RELM1; j++) a[j] /= ssum;
        for (int c = 0; c < C; c++) {
            float s = 0.f;
            for (int j = 0; j < N_RELM1; j++) s += a[j] * weight[j * C + c];
            g_dw[f * C + c] = s;
        }
    }
    if (t == 64) {
        float rowsum[N_FACT];
        for (int f = 0; f < N_FACT; f++) {
            float s = 0.f;
            for (int j = 0; j < N_RELM1; j++) s += att[f * N_RELM1 + j];
            rowsum[f] = s;
        }
        float cor = 0.f;
        for (int r = 0; r < N_RELM1; r++) {
            float ss = 0.f, ttl = 0.f;
            for (int f = 0; f < N_FACT; f++) {
                float v = att[f * N_RELM1 + r];
                ss += v * v; ttl += v * rowsum[f];
            }
            float n = sqrtf(ss);
            float pos = 0.f;
            for (int f = 0; f < N_FACT; f++) {
                float v = att[f * N_RELM1 + r] / n; pos += v * v;
            }
            cor += (ttl - pos) / TEMPR;
        }
        *out_cor = cor;
    }
    if (t == 65) {
        g_offE[N_ENT] = N_EDGE;
        g_offU[N_USR] = N_EDGE;
    }
}

// ---------------- count (+prep, +fp16 staging) ----------------
__global__ void k_count(const int* __restrict__ head, const int* __restrict__ urows,
                        const float* __restrict__ weight, const float* __restrict__ kgW,
                        const float* __restrict__ att, float* __restrict__ out_cor,
                        const float* __restrict__ ent) {
    __shared__ float sPrep[C * C + N_RELM1 * C];
    if (blockIdx.x == EB) {
        prep_body(weight, kgW, att, out_cor, sPrep, sPrep + C * C);
        return;
    }
    if (blockIdx.x > EB) {   // fp16 staging of entity_emb
        int i4 = (blockIdx.x - EB - 1) * 256 + threadIdx.x;
        float4 v = __ldg(&reinterpret_cast<const float4*>(ent)[i4]);
        uint2 u = make_uint2(h2bits(__floats2half2_rn(v.x, v.y)),
                             h2bits(__floats2half2_rn(v.z, v.w)));
        reinterpret_cast<uint2*>(g_entH)[i4] = u;
        return;
    }
    int e = blockIdx.x * blockDim.x + threadIdx.x;
    if (e >= N_EDGE) return;
    atomicAdd(&g_cntE[head[e]], 1);
    atomicAdd(&g_cntU[urows[e]], 1);
}

// ---------------- scan (decoupled lookback) + score-table blocks ----------------
// scan blocks: bids [0, NB_E+NB_U); score blocks: bids [NB_E+NB_U, +SBK)
// 245 x 1024-thread blocks <= 296 capacity -> scan blocks co-resident (safe lookback)
__global__ void __launch_bounds__(SCAN_B) k_scan(const float* __restrict__ ent) {
    __shared__ __align__(16) float sMem[SCAN_B];    // scan ints / sVT floats
    if (blockIdx.x >= NB_E + NB_U) {
        // score-table: thread-per-entity me = exp(E . V_r); g_V ready (k_count prep)
        float (*sVT)[12] = reinterpret_cast<float(*)[12]>(sMem);   // [C][12]
        int t = threadIdx.x;
        for (int i = t; i < N_RELM1 * C; i += SCAN_B) {
            int r = i / C, c = i % C;
            sVT[c][r] = g_V[i];
        }
        __syncthreads();
        int entI = (blockIdx.x - NB_E - NB_U) * SCAN_B + t;
        if (entI >= N_ENT) return;
        float acc[12];
#pragma unroll
        for (int r = 0; r < 12; r++) acc[r] = 0.f;
        const float4* row = &reinterpret_cast<const float4*>(ent)[(size_t)entI * 16];
#pragma unroll 4
        for (int k4 = 0; k4 < 16; k4++) {
            float4 v = __ldg(&row[k4]);
            int c = k4 * 4;
            const float4* vt0 = reinterpret_cast<const float4*>(&sVT[c][0]);
            const float4* vt1 = reinterpret_cast<const float4*>(&sVT[c + 1][0]);
            const float4* vt2 = reinterpret_cast<const float4*>(&sVT[c + 2][0]);
            const float4* vt3 = reinterpret_cast<const float4*>(&sVT[c + 3][0]);
#pragma unroll
            for (int j = 0; j < 3; j++) {
                float4 a0 = vt0[j], a1 = vt1[j], a2 = vt2[j], a3 = vt3[j];
                acc[j*4+0] += v.x*a0.x + v.y*a1.x + v.z*a2.x + v.w*a3.x;
                acc[j*4+1] += v.x*a0.y + v.y*a1.y + v.z*a2.y + v.w*a3.y;
                acc[j*4+2] += v.x*a0.z + v.y*a1.z + v.z*a2.z + v.w*a3.z;
                acc[j*4+3] += v.x*a0.w + v.y*a1.w + v.z*a2.w + v.w*a3.w;
            }
        }
#pragma unroll
        for (int r = 0; r < N_RELM1; r++)
            g_Sme[(size_t)entI * 12 + r] = __expf(acc[r]);
        return;
    }
    int* sh = reinterpret_cast<int*>(sMem);
    __shared__ int sbp;
    bool isE = blockIdx.x < NB_E;
    int b = isE ? blockIdx.x : blockIdx.x - NB_E;
    int n = isE ? N_ENT : N_USR;
    int* cnt  = isE ? g_cntE : g_cntU;
    int* off  = isE ? g_offE : g_offU;
    int* cur  = isE ? g_curE : g_curU;
    int* bsum = isE ? g_bsumE : g_bsumU;
    int* brdy = isE ? g_brdyE : g_brdyU;
    int t = threadIdx.x;
    int i = b * SCAN_B + t;
    int v = (i < n) ? cnt[i] : 0;
    if (i < n) cnt[i] = 0;              // self-zero for next call
    sh[t] = v;
    __syncthreads();
    for (int d = 1; d < SCAN_B; d <<= 1) {
        int u = (t >= d) ? sh[t - d] : 0;
        __syncthreads();
        sh[t] += u;
        __syncthreads();
    }
    int incl = sh[t];
    if (t == SCAN_B - 1) {
        bsum[b] = incl;
        __threadfence();
        atomicExch(&brdy[b], 1);
    }
    if (t < 32) {
        int s = 0;
        for (int j = t; j < b; j += 32) {
            while (atomicAdd(&brdy[j], 0) == 0) { }
            s += atomicAdd(&bsum[j], 0);
        }
#pragma unroll
        for (int o = 16; o; o >>= 1) s += __shfl_xor_sync(0xffffffffu, s, o);
        if (t == 0) sbp = s;
    }
    __syncthreads();
    if (i < n) {
        int o = sbp + incl - v;
        off[i] = o;
        cur[i] = o;
    }
}

// ---------------- fill: CSR payloads + histogram ----------------
__global__ void k_fill(const int* __restrict__ head, const int* __restrict__ tail,
                       const int* __restrict__ etype, const int* __restrict__ urows,
                       const int* __restrict__ ucols, const float* __restrict__ uvals) {
    if (blockIdx.x == 0 && threadIdx.x < 128) {
        g_brdyE[threadIdx.x] = 0;
        g_brdyU[threadIdx.x] = 0;
    }
    int e = blockIdx.x * blockDim.x + threadIdx.x;
    if (e >= N_EDGE) return;
    int h = head[e];
    int ty = etype[e] - 1;
    int p = atomicAdd(&g_curE[h], 1);
    g_pkm[p].x = tail[e] | (ty << 20);
    atomicAdd(&g_histE[h], 1ULL << (7 * ty));    // deg<=127 per type: safe
    int q = atomicAdd(&g_curU[urows[e]], 1);
    g_uiP[q] = make_int2(ucols[e], __float_as_int(uvals[e]));
}

// ---------------- helpers ----------------
__device__ __forceinline__ float dot4(float4 a, float4 b) {
    return a.x * b.x + a.y * b.y + a.z * b.z + a.w * b.w;
}
__device__ __forceinline__ float red16(float p, unsigned m) {
    p += __shfl_xor_sync(m, p, 1);
    p += __shfl_xor_sync(m, p, 2);
    p += __shfl_xor_sync(m, p, 4);
    p += __shfl_xor_sync(m, p, 8);
    return p;
}

// ---------------- kg0 device body ----------------
__device__ __forceinline__ void kg0_body(int blk, int t,
                                         const float* __restrict__ ent,
                                         float* __restrict__ out_ent,
                                         const ulonglong2* sW,
                                         const float* sWn) {
    int w = blk * 8 + (t >> 5);           // KGB*8 == N_ENT exactly
    int lane = t & 31, half = lane >> 4, l = lane & 15;
    unsigned hm = 0xFFFFu << (half * 16);
    int off = g_offE[w], deg = g_offE[w + 1] - off;

    ulonglong2 hv = __ldg(&reinterpret_cast<const ulonglong2*>(ent)[(size_t)w * 16 + l]);

    // me = exp(hv . V_l) precomputed in k_scan's score-table blocks
    float me = (l < N_RELM1) ? __ldg(&g_Sme[(size_t)w * 12 + l]) : 0.f;

    // s1 from the type histogram
    u64 hist = g_histE[w];
    if (lane == 0) g_histE[w] = 0ULL;     // self-zero for next call
    int sh7 = 7 * ((l < N_RELM1) ? l : 0);
    float part = (l < N_RELM1) ? (float)(int)((hist >> sh7) & 127ULL) * me : 0.f;
    float s1 = red16(part, hm);
    float inv1 = 1.f / (s1 + 1e-16f);
    float q = me * inv1;
    q = q * q * ((l < N_RELM1) ? sWn[l] : 0.f);

    ulonglong2 acc; acc.x = 0ULL; acc.y = 0ULL;
#pragma unroll 2
    for (int i = half; i < deg; i += 2) {
        int pk = __ldg(&g_pkm[off + i].x);
        int ty = pk >> 20;
        int tl = pk & 0xFFFFF;
        uint2 raw = __ldg(&reinterpret_cast<const uint2*>(g_entH)[(size_t)tl * 16 + l]);
        ulonglong2 tv; tv.x = h2f2(raw.x); tv.y = h2f2(raw.y);
        float ht = red16(p2dot(hv, tv), hm);
        float e2 = __expf(ht + __shfl_sync(hm, q, ty, 16));
        ulonglong2 wv = sW[ty * 16 + l];
        u64 e2p = f2bcast(e2);
        acc.x = f2fma(f2mul(tv.x, wv.x), e2p, acc.x);
        acc.y = f2fma(f2mul(tv.y, wv.y), e2p, acc.y);
        if (l == 0) g_pkm[off + i].y = __float_as_int(e2);
    }
    __syncwarp();
    float2 a0 = f2up(acc.x), a1 = f2up(acc.y);
    float4 a = make_float4(a0.x, a0.y, a1.x, a1.y);
    a.x += __shfl_xor_sync(0xffffffffu, a.x, 16);
    a.y += __shfl_xor_sync(0xffffffffu, a.y, 16);
    a.z += __shfl_xor_sync(0xffffffffu, a.z, 16);
    a.w += __shfl_xor_sync(0xffffffffu, a.w, 16);

    float ss = red16(dot4(a, a), 0xffffffffu);
    float inv = 1.f / fmaxf(sqrtf(ss), 1e-12f);
    float4 x = make_float4(a.x * inv, a.y * inv, a.z * inv, a.w * inv);
    if (half == 0) {
        uint2 u = make_uint2(h2bits(__floats2half2_rn(x.x, x.y)),
                             h2bits(__floats2half2_rn(x.z, x.w)));
        reinterpret_cast<uint2*>(g_entAH)[(size_t)w * 16 + l] = u;
        float2 h0 = f2up(hv.x), h1 = f2up(hv.y);
        float4 o = make_float4(h0.x + x.x, h0.y + x.y, h1.x + x.z, h1.y + x.w);
        reinterpret_cast<float4*>(out_ent)[(size_t)w * 16 + l] = o;
    }
}

// ---------------- kg1 device body ----------------
__device__ __forceinline__ void kg1_body(int blk, int t,
                                         float* __restrict__ out_ent,
                                         const ulonglong2* sW) {
    int w = blk * 8 + (t >> 5);
    int lane = t & 31, half = lane >> 4, l = lane & 15;
    int off = g_offE[w], deg = g_offE[w + 1] - off;

    ulonglong2 acc; acc.x = 0ULL; acc.y = 0ULL;
#pragma unroll 2
    for (int i = half; i < deg; i += 2) {
        int2 pm = __ldg(&g_pkm[off + i]);
        int ty = pm.x >> 20;
        int tl = pm.x & 0xFFFFF;
        float m = __int_as_float(pm.y);
        uint2 raw = __ldg(&reinterpret_cast<const uint2*>(g_entAH)[(size_t)tl * 16 + l]);
        ulonglong2 wv = sW[ty * 16 + l];
        u64 mp = f2bcast(m);
        acc.x = f2fma(f2mul(h2f2(raw.x), wv.x), mp, acc.x);
        acc.y = f2fma(f2mul(h2f2(raw.y), wv.y), mp, acc.y);
    }
    __syncwarp();
    float2 a0 = f2up(acc.x), a1 = f2up(acc.y);
    float4 a = make_float4(a0.x, a0.y, a1.x, a1.y);
    a.x += __shfl_xor_sync(0xffffffffu, a.x, 16);
    a.y += __shfl_xor_sync(0xffffffffu, a.y, 16);
    a.z += __shfl_xor_sync(0xffffffffu, a.z, 16);
    a.w += __shfl_xor_sync(0xffffffffu, a.w, 16);

    float ss = red16(dot4(a, a), 0xffffffffu);
    float inv = 1.f / fmaxf(sqrtf(ss), 1e-12f);
    if (half == 0) {
        float4 o = reinterpret_cast<const float4*>(out_ent)[(size_t)w * 16 + l];
        o.x += a.x * inv; o.y += a.y * inv;
        o.z += a.z * inv; o.w += a.w * inv;
        reinterpret_cast<float4*>(out_ent)[(size_t)w * 16 + l] = o;
    }
}

// ---------------- ui device body ----------------
template <int HOP>
__device__ __forceinline__ void ui_body(int blk, int t,
                                        const float* __restrict__ user_emb,
                                        float* __restrict__ out_usr,
                                        const float4* sL, const float4* sD) {
    int u = blk * 8 + (t >> 5);           // UIB*8 == N_USR exactly
    int lane = t & 31, half = lane >> 4, l = lane & 15;
    unsigned hm = 0xFFFFu << (half * 16);
    const float*  usr_src = (HOP == 0) ? user_emb : g_usrA;
    const __half* entH    = (HOP == 0) ? g_entH : g_entAH;

    float4 uv = __ldg(&reinterpret_cast<const float4*>(usr_src)[(size_t)u * 16 + l]);

    float d0 = red16(dot4(uv, sL[0 * 16 + l]), hm);
    float d1 = red16(dot4(uv, sL[1 * 16 + l]), hm);
    float d2 = red16(dot4(uv, sL[2 * 16 + l]), hm);
    float d3 = red16(dot4(uv, sL[3 * 16 + l]), hm);
    float m = fmaxf(fmaxf(d0, d1), fmaxf(d2, d3));
    d0 = __expf(d0 - m); d1 = __expf(d1 - m); d2 = __expf(d2 - m); d3 = __expf(d3 - m);
    float invs = 1.f / (d0 + d1 + d2 + d3);
    d0 *= invs; d1 *= invs; d2 *= invs; d3 *= invs;

    int off = g_offU[u], deg = g_offU[u + 1] - off;
    ulonglong2 acc; acc.x = 0ULL; acc.y = 0ULL;
#pragma unroll 2
    for (int i = half; i < deg; i += 2) {
        int2 p = __ldg(&g_uiP[off + i]);
        u64 vp = f2bcast(__int_as_float(p.y));
        uint2 raw = __ldg(&reinterpret_cast<const uint2*>(entH)[(size_t)p.x * 16 + l]);
        acc.x = f2fma(h2f2(raw.x), vp, acc.x);
        acc.y = f2fma(h2f2(raw.y), vp, acc.y);
    }
    __syncwarp();
    float2 c0 = f2up(acc.x), c1 = f2up(acc.y);
    float4 a = make_float4(c0.x, c0.y, c1.x, c1.y);
    a.x += __shfl_xor_sync(0xffffffffu, a.x, 16);
    a.y += __shfl_xor_sync(0xffffffffu, a.y, 16);
    a.z += __shfl_xor_sync(0xffffffffu, a.z, 16);
    a.w += __shfl_xor_sync(0xffffffffu, a.w, 16);

    float4 b0 = sD[0 * 16 + l], b1 = sD[1 * 16 + l], b2 = sD[2 * 16 + l], b3 = sD[3 * 16 + l];
    float4 mix;
    mix.x = 1.f + d0 * b0.x + d1 * b1.x + d2 * b2.x + d3 * b3.x;
    mix.y = 1.f + d0 * b0.y + d1 * b1.y + d2 * b2.y + d3 * b3.y;
    mix.z = 1.f + d0 * b0.z + d1 * b1.z + d2 * b2.z + d3 * b3.z;
    mix.w = 1.f + d0 * b0.w + d1 * b1.w + d2 * b2.w + d3 * b3.w;

    float4 x = make_float4(a.x * mix.x, a.y * mix.y, a.z * mix.z, a.w * mix.w);
    float ss = red16(dot4(x, x), 0xffffffffu);
    float inv = 1.f / fmaxf(sqrtf(ss), 1e-12f);
    x.x *= inv; x.y *= inv; x.z *= inv; x.w *= inv;

    if (half == 0) {
        if (HOP == 0) {
            reinterpret_cast<float4*>(g_usrA)[(size_t)u * 16 + l] = x;
            float4 o = make_float4(uv.x + x.x, uv.y + x.y, uv.z + x.z, uv.w + x.w);
            reinterpret_cast<float4*>(out_usr)[(size_t)u * 16 + l] = o;
        } else {
            float4 o = reinterpret_cast<const float4*>(out_usr)[(size_t)u * 16 + l];
            o.x += x.x; o.y += x.y; o.z += x.z; o.w += x.w;
            reinterpret_cast<float4*>(out_usr)[(size_t)u * 16 + l] = o;
        }
    }
}

// ---------------- fused hop kernels (8 CTAs/SM) ----------------
__global__ void __launch_bounds__(256, 8) k_fused0(const float* __restrict__ ent,
                                                   const float* __restrict__ usr,
                                                   const float* __restrict__ latent,
                                                   const float* __restrict__ weight,
                                                   float* __restrict__ out_ent,
                                                   float* __restrict__ out_usr) {
    __shared__ float4 sA[N_RELM1 * 16];
    __shared__ float4 sB[N_RELM1 * 16];
    __shared__ float  sWn[N_RELM1];
    int t = threadIdx.x;
    bool isKG = blockIdx.x < KGB;
    if (isKG) {
        for (int i = t; i < N_RELM1 * 16; i += 256)
            sB[i] = reinterpret_cast<const float4*>(weight)[i];
        if (t < N_RELM1) sWn[t] = g_wn2[t];
    } else {
        for (int i = t; i < N_FACT * 16; i += 256) {
            sA[i] = reinterpret_cast<const float4*>(latent)[i];
            sB[i] = reinterpret_cast<const float4*>(g_dw)[i];
        }
    }
    __syncthreads();
    if (isKG) kg0_body(blockIdx.x, t, ent, out_ent,
                       reinterpret_cast<const ulonglong2*>(sB), sWn);
    else      ui_body<0>(blockIdx.x - KGB, t, usr, out_usr, sA, sB);
}

__global__ void __launch_bounds__(256, 8) k_fused1(const float* __restrict__ usr,
                                                   const float* __restrict__ latent,
                                                   const float* __restrict__ weight,
                                                   float* __restrict__ out_ent,
                                                   float* __restrict__ out_usr) {
    __shared__ float4 sA[N_RELM1 * 16];
    __shared__ float4 sB[N_RELM1 * 16];
    int t = threadIdx.x;
    bool isKG = blockIdx.x < KGB;
    if (isKG) {
        for (int i = t; i < N_RELM1 * 16; i += 256)
            sB[i] = reinterpret_cast<const float4*>(weight)[i];
    } else {
        for (int i = t; i < N_FACT * 16; i += 256) {
            sA[i] = reinterpret_cast<const float4*>(latent)[i];
            sB[i] = reinterpret_cast<const float4*>(g_dw)[i];
        }
    }
    __syncthreads();
    if (isKG) kg1_body(blockIdx.x, t, out_ent,
                       reinterpret_cast<const ulonglong2*>(sB));
    else      ui_body<1>(blockIdx.x - KGB, t, usr, out_usr, sA, sB);
}

// ---------------- launch ----------------
extern "C" void kernel_launch(void* const* d_in, const int* in_sizes, int n_in,
                              void* d_out, int out_size) {
    const float* user_emb   = (const float*)d_in[0];
    const float* entity_emb = (const float*)d_in[1];
    const float* latent     = (const float*)d_in[2];
    const float* weight     = (const float*)d_in[3];
    const float* att        = (const float*)d_in[4];
    const float* kgW        = (const float*)d_in[5];
    const float* ui_vals    = (const float*)d_in[6];
    const int*   edge_index = (const int*)d_in[7];
    const int*   etype      = (const int*)d_in[8];
    const int*   ui_rows    = (const int*)d_in[9];
    const int*   ui_cols    = (const int*)d_in[10];

    const int* head = edge_index;
    const int* tail = edge_index + N_EDGE;

    float* out     = (float*)d_out;
    float* out_ent = out;
    float* out_usr = out + (size_t)N_ENT * C;
    float* out_cor = out + (size_t)N_ENT * C + (size_t)N_USR * C;

    const int TB = 256;

    k_count<<<EB + 1 + HB, TB>>>(head, ui_rows, weight, kgW, att, out_cor,
                                 entity_emb);                            // 1 (+prep+stage)
    k_scan<<<NB_E + NB_U + SBK, SCAN_B>>>(entity_emb);                   // 2 (+score table)
    k_fill<<<EB, TB>>>(head, tail, etype, ui_rows, ui_cols, ui_vals);    // 3 (+hist)
    k_fused0<<<KGB + UIB, TB>>>(entity_emb, user_emb, latent, weight,    // 4 (profiled)
                                out_ent, out_usr);
    k_fused1<<<KGB + UIB, TB>>>(user_emb, latent, weight,                // 5
                                out_ent, out_usr);
}

// round 15
// speedup vs baseline: 1.0406x; 1.0406x over previous
#include <cuda_runtime.h>
#include <cuda_fp16.h>
#include <math_constants.h>

#define N_ENT   100000
#define N_USR   50000
#define N_EDGE  1000000
#define C       64
#define N_FACT  4
#define N_RELM1 9
#define TEMPR   0.2f
// 1 / (2*sqrt(32))
#define INV_SCALE 0.08838834764831845f

#define SCAN_B  1024
#define NB_E    ((N_ENT + SCAN_B - 1) / SCAN_B)   // 98
#define NB_U    ((N_USR + SCAN_B - 1) / SCAN_B)   // 49
#define SBK     ((N_ENT + SCAN_B - 1) / SCAN_B)   // 98 score blocks (1024 ent each)

#define KGB     (N_ENT * 32 / 256)                // 12500 blocks (exact)
#define UIB     (N_USR * 32 / 256)                // 6250 blocks (exact)
#define EB      ((N_EDGE + 255) / 256)            // 3907 edge blocks
#define HB      (N_ENT * C / 4 / 256)             // 6250 fp16-staging blocks

typedef unsigned long long u64;

// ---------------- scratch (device globals; no allocation) ----------------
__device__ __align__(16) float g_V[N_RELM1 * C];     // W W^T w^T, pre-scaled
__device__ float g_wn2[N_RELM1];
__device__ __align__(16) float g_dw[N_FACT * C];     // softmax(att) @ weight
__device__ __align__(16) float g_Sme[N_ENT * 12];    // exp(E·V_r), padded to 12
__device__ __align__(8) __half g_entH[N_ENT * C];    // fp16 copy of entity_emb
__device__ __align__(8) __half g_entAH[N_ENT * C];   // fp16 ent after hop0 norm
__device__ __align__(16) float g_usrA[N_USR * C];    // usr after hop0 norm (fp32)
__device__ float g_mask[N_EDGE];                     // unnormalized e2 per CSR pos
__device__ u64 g_histE[N_ENT];                       // packed per-head type histogram
__device__ int g_cntE[N_ENT], g_curE[N_ENT];
__device__ int g_cntU[N_USR], g_curU[N_USR];
__device__ int g_offE[N_ENT + 1];
__device__ int g_offU[N_USR + 1];
__device__ int  g_pkE[N_EDGE];                       // CSR-ordered (tail | type<<20)
__device__ __align__(8) int2 g_uiP[N_EDGE];          // CSR-ordered (col, val bits)
__device__ int g_bsumE[128], g_brdyE[128];
__device__ int g_bsumU[128], g_brdyU[128];

// ---------------- packed f32x2 helpers (sm_103a FFMA2 path) ----------------
__device__ __forceinline__ u64 f2mul(u64 x, u64 y) {
    u64 d; asm("mul.rn.f32x2 %0,%1,%2;" : "=l"(d) : "l"(x), "l"(y)); return d;
}
__device__ __forceinline__ u64 f2fma(u64 x, u64 y, u64 c) {
    u64 d; asm("fma.rn.f32x2 %0,%1,%2,%3;" : "=l"(d) : "l"(x), "l"(y), "l"(c)); return d;
}
__device__ __forceinline__ u64 f2bcast(float v) {
    u64 d; asm("mov.b64 %0,{%1,%1};" : "=l"(d) : "f"(v)); return d;
}
__device__ __forceinline__ float2 f2up(u64 v) {
    float2 f; asm("mov.b64 {%0,%1},%2;" : "=f"(f.x), "=f"(f.y) : "l"(v)); return f;
}
__device__ __forceinline__ float p2dot(ulonglong2 a, ulonglong2 b) {
    u64 d = f2mul(a.x, b.x);
    d = f2fma(a.y, b.y, d);
    float2 f = f2up(d);
    return f.x + f.y;
}
// half2 bits -> packed f32x2 (u64)
__device__ __forceinline__ u64 h2f2(unsigned h) {
    __half2 hh = *reinterpret_cast<__half2*>(&h);
    float2 f = __half22float2(hh);
    u64 d; asm("mov.b64 %0,{%1,%2};" : "=l"(d) : "f"(f.x), "f"(f.y));
    return d;
}
__device__ __forceinline__ unsigned h2bits(__half2 h) {
    return *reinterpret_cast<unsigned*>(&h);
}

// ---------------- prep body (runs as extra block of count) ----------------
__device__ void prep_body(const float* __restrict__ weight,
                          const float* __restrict__ kgW,
                          const float* __restrict__ att,
                          float* __restrict__ out_cor,
                          float* sW, float* sWk) {
    int t = threadIdx.x;
    int nt = blockDim.x;
    for (int i = t; i < C * C; i += nt) sW[i] = kgW[i];
    __syncthreads();
    for (int i = t; i < N_RELM1 * C; i += nt) {
        int r = i / C, k = i % C;
        float s = 0.f;
        for (int c = 0; c < C; c++) s += weight[r * C + c] * sW[c * C + k];
        sWk[i] = s;
    }
    __syncthreads();
    for (int i = t; i < N_RELM1 * C; i += nt) {
        int r = i / C, c = i % C;
        float s = 0.f;
        for (int k = 0; k < C; k++) s += sW[c * C + k] * sWk[r * C + k];
        g_V[i] = s * INV_SCALE;
    }
    if (t < N_RELM1) {
        float s = 0.f;
        for (int c = 0; c < C; c++) { float w = weight[t * C + c]; s += w * w; }
        g_wn2[t] = s;
    }
    if (t >= 32 && t < 32 + N_FACT) {
        int f = t - 32;
        float a[N_RELM1]; float m = -CUDART_INF_F;
        for (int j = 0; j < N_RELM1; j++) { a[j] = att[f * N_RELM1 + j]; m = fmaxf(m, a[j]); }
        float ssum = 0.f;
        for (int j = 0; j < N_RELM1; j++) { a[j] = expf(a[j] - m); ssum += a[j]; }
        for (int j = 0; j < N_RELM1; j++) a[j] /= ssum;
        for (int c = 0; c < C; c++) {
            float s = 0.f;
            for (int j = 0; j < N_RELM1; j++) s += a[j] * weight[j * C + c];
            g_dw[f * C + c] = s;
        }
    }
    if (t == 64) {
        float rowsum[N_FACT];
        for (int f = 0; f < N_FACT; f++) {
            float s = 0.f;
            for (int j = 0; j < N_RELM1; j++) s += att[f * N_RELM1 + j];
            rowsum[f] = s;
        }
        float cor = 0.f;
        for (int r = 0; r < N_RELM1; r++) {
            float ss = 0.f, ttl = 0.f;
            for (int f = 0; f < N_FACT; f++) {
                float v = att[f * N_RELM1 + r];
                ss += v * v; ttl += v * rowsum[f];
            }
            float n = sqrtf(ss);
            float pos = 0.f;
            for (int f = 0; f < N_FACT; f++) {
                float v = att[f * N_RELM1 + r] / n; pos += v * v;
            }
            cor += (ttl - pos) / TEMPR;
        }
        *out_cor = cor;
    }
    if (t == 65) {
        g_offE[N_ENT] = N_EDGE;
        g_offU[N_USR] = N_EDGE;
    }
}

// ---------------- count (+prep, +fp16 staging) ----------------
__global__ void k_count(const int* __restrict__ head, const int* __restrict__ urows,
                        const float* __restrict__ weight, const float* __restrict__ kgW,
                        const float* __restrict__ att, float* __restrict__ out_cor,
                        const float* __restrict__ ent) {
    __shared__ float sPrep[C * C + N_RELM1 * C];
    if (blockIdx.x == EB) {
        prep_body(weight, kgW, att, out_cor, sPrep, sPrep + C * C);
        return;
    }
    if (blockIdx.x > EB) {   // fp16 staging of entity_emb
        int i4 = (blockIdx.x - EB - 1) * 256 + threadIdx.x;
        float4 v = __ldg(&reinterpret_cast<const float4*>(ent)[i4]);
        uint2 u = make_uint2(h2bits(__floats2half2_rn(v.x, v.y)),
                             h2bits(__floats2half2_rn(v.z, v.w)));
        reinterpret_cast<uint2*>(g_entH)[i4] = u;
        return;
    }
    int e = blockIdx.x * blockDim.x + threadIdx.x;
    if (e >= N_EDGE) return;
    atomicAdd(&g_cntE[head[e]], 1);
    atomicAdd(&g_cntU[urows[e]], 1);
}

// ---------------- scan (decoupled lookback) + score-table blocks ----------------
// scan blocks: bids [0, NB_E+NB_U); score blocks: bids [NB_E+NB_U, +SBK)
// 245 x 1024-thread blocks <= 296 capacity -> scan blocks co-resident (safe lookback)
__global__ void __launch_bounds__(SCAN_B) k_scan(const float* __restrict__ ent) {
    __shared__ __align__(16) float sMem[SCAN_B];    // scan ints / sVT floats
    if (blockIdx.x >= NB_E + NB_U) {
        // score-table: thread-per-entity me = exp(E . V_r); g_V ready (k_count prep)
        float (*sVT)[12] = reinterpret_cast<float(*)[12]>(sMem);   // [C][12]
        int t = threadIdx.x;
        for (int i = t; i < N_RELM1 * C; i += SCAN_B) {
            int r = i / C, c = i % C;
            sVT[c][r] = g_V[i];
        }
        __syncthreads();
        int entI = (blockIdx.x - NB_E - NB_U) * SCAN_B + t;
        if (entI >= N_ENT) return;
        float acc[12];
#pragma unroll
        for (int r = 0; r < 12; r++) acc[r] = 0.f;
        const float4* row = &reinterpret_cast<const float4*>(ent)[(size_t)entI * 16];
#pragma unroll 4
        for (int k4 = 0; k4 < 16; k4++) {
            float4 v = __ldg(&row[k4]);
            int c = k4 * 4;
            const float4* vt0 = reinterpret_cast<const float4*>(&sVT[c][0]);
            const float4* vt1 = reinterpret_cast<const float4*>(&sVT[c + 1][0]);
            const float4* vt2 = reinterpret_cast<const float4*>(&sVT[c + 2][0]);
            const float4* vt3 = reinterpret_cast<const float4*>(&sVT[c + 3][0]);
#pragma unroll
            for (int j = 0; j < 3; j++) {
                float4 a0 = vt0[j], a1 = vt1[j], a2 = vt2[j], a3 = vt3[j];
                acc[j*4+0] += v.x*a0.x + v.y*a1.x + v.z*a2.x + v.w*a3.x;
                acc[j*4+1] += v.x*a0.y + v.y*a1.y + v.z*a2.y + v.w*a3.y;
                acc[j*4+2] += v.x*a0.z + v.y*a1.z + v.z*a2.z + v.w*a3.z;
                acc[j*4+3] += v.x*a0.w + v.y*a1.w + v.z*a2.w + v.w*a3.w;
            }
        }
#pragma unroll
        for (int r = 0; r < N_RELM1; r++)
            g_Sme[(size_t)entI * 12 + r] = __expf(acc[r]);
        return;
    }
    int* sh = reinterpret_cast<int*>(sMem);
    __shared__ int sbp;
    bool isE = blockIdx.x < NB_E;
    int b = isE ? blockIdx.x : blockIdx.x - NB_E;
    int n = isE ? N_ENT : N_USR;
    int* cnt  = isE ? g_cntE : g_cntU;
    int* off  = isE ? g_offE : g_offU;
    int* cur  = isE ? g_curE : g_curU;
    int* bsum = isE ? g_bsumE : g_bsumU;
    int* brdy = isE ? g_brdyE : g_brdyU;
    int t = threadIdx.x;
    int i = b * SCAN_B + t;
    int v = (i < n) ? cnt[i] : 0;
    if (i < n) cnt[i] = 0;              // self-zero for next call
    sh[t] = v;
    __syncthreads();
    for (int d = 1; d < SCAN_B; d <<= 1) {
        int u = (t >= d) ? sh[t - d] : 0;
        __syncthreads();
        sh[t] += u;
        __syncthreads();
    }
    int incl = sh[t];
    if (t == SCAN_B - 1) {
        bsum[b] = incl;
        __threadfence();
        atomicExch(&brdy[b], 1);
    }
    if (t < 32) {
        int s = 0;
        for (int j = t; j < b; j += 32) {
            while (atomicAdd(&brdy[j], 0) == 0) { }
            s += atomicAdd(&bsum[j], 0);
        }
#pragma unroll
        for (int o = 16; o; o >>= 1) s += __shfl_xor_sync(0xffffffffu, s, o);
        if (t == 0) sbp = s;
    }
    __syncthreads();
    if (i < n) {
        int o = sbp + incl - v;
        off[i] = o;
        cur[i] = o;
    }
}

// ---------------- fill: CSR payloads + histogram ----------------
__global__ void k_fill(const int* __restrict__ head, const int* __restrict__ tail,
                       const int* __restrict__ etype, const int* __restrict__ urows,
                       const int* __restrict__ ucols, const float* __restrict__ uvals) {
    if (blockIdx.x == 0 && threadIdx.x < 128) {
        g_brdyE[threadIdx.x] = 0;
        g_brdyU[threadIdx.x] = 0;
    }
    int e = blockIdx.x * blockDim.x + threadIdx.x;
    if (e >= N_EDGE) return;
    int h = head[e];
    int ty = etype[e] - 1;
    int p = atomicAdd(&g_curE[h], 1);
    g_pkE[p] = tail[e] | (ty << 20);
    atomicAdd(&g_histE[h], 1ULL << (7 * ty));    // deg<=127 per type: safe
    int q = atomicAdd(&g_curU[urows[e]], 1);
    g_uiP[q] = make_int2(ucols[e], __float_as_int(uvals[e]));
}

// ---------------- helpers ----------------
__device__ __forceinline__ float dot4(float4 a, float4 b) {
    return a.x * b.x + a.y * b.y + a.z * b.z + a.w * b.w;
}
__device__ __forceinline__ float red16(float p, unsigned m) {
    p += __shfl_xor_sync(m, p, 1);
    p += __shfl_xor_sync(m, p, 2);
    p += __shfl_xor_sync(m, p, 4);
    p += __shfl_xor_sync(m, p, 8);
    return p;
}

// ---------------- kg0 device body ----------------
__device__ __forceinline__ void kg0_body(int blk, int t,
                                         const float* __restrict__ ent,
                                         float* __restrict__ out_ent,
                                         const ulonglong2* sW,
                                         const float* sWn) {
    int w = blk * 8 + (t >> 5);           // KGB*8 == N_ENT exactly
    int lane = t & 31, half = lane >> 4, l = lane & 15;
    unsigned hm = 0xFFFFu << (half * 16);
    int off = g_offE[w], deg = g_offE[w + 1] - off;

    ulonglong2 hv = __ldg(&reinterpret_cast<const ulonglong2*>(ent)[(size_t)w * 16 + l]);

    // me = exp(hv . V_l) precomputed in k_scan's score-table blocks
    float me = (l < N_RELM1) ? __ldg(&g_Sme[(size_t)w * 12 + l]) : 0.f;

    // s1 from the type histogram
    u64 hist = g_histE[w];
    if (lane == 0) g_histE[w] = 0ULL;     // self-zero for next call
    int sh7 = 7 * ((l < N_RELM1) ? l : 0);
    float part = (l < N_RELM1) ? (float)(int)((hist >> sh7) & 127ULL) * me : 0.f;
    float s1 = red16(part, hm);
    float inv1 = 1.f / (s1 + 1e-16f);
    float q = me * inv1;
    q = q * q * ((l < N_RELM1) ? sWn[l] : 0.f);

    ulonglong2 acc; acc.x = 0ULL; acc.y = 0ULL;
#pragma unroll 2
    for (int i = half; i < deg; i += 2) {
        int pk = __ldg(&g_pkE[off + i]);
        int ty = pk >> 20;
        int tl = pk & 0xFFFFF;
        uint2 raw = __ldg(&reinterpret_cast<const uint2*>(g_entH)[(size_t)tl * 16 + l]);
        ulonglong2 tv; tv.x = h2f2(raw.x); tv.y = h2f2(raw.y);
        float ht = red16(p2dot(hv, tv), hm);
        float e2 = __expf(ht + __shfl_sync(hm, q, ty, 16));
        ulonglong2 wv = sW[ty * 16 + l];
        u64 e2p = f2bcast(e2);
        acc.x = f2fma(f2mul(tv.x, wv.x), e2p, acc.x);
        acc.y = f2fma(f2mul(tv.y, wv.y), e2p, acc.y);
        if (l == 0) g_mask[off + i] = e2;
    }
    __syncwarp();
    float2 a0 = f2up(acc.x), a1 = f2up(acc.y);
    float4 a = make_float4(a0.x, a0.y, a1.x, a1.y);
    a.x += __shfl_xor_sync(0xffffffffu, a.x, 16);
    a.y += __shfl_xor_sync(0xffffffffu, a.y, 16);
    a.z += __shfl_xor_sync(0xffffffffu, a.z, 16);
    a.w += __shfl_xor_sync(0xffffffffu, a.w, 16);

    float ss = red16(dot4(a, a), 0xffffffffu);
    float inv = 1.f / fmaxf(sqrtf(ss), 1e-12f);
    float4 x = make_float4(a.x * inv, a.y * inv, a.z * inv, a.w * inv);
    if (half == 0) {
        uint2 u = make_uint2(h2bits(__floats2half2_rn(x.x, x.y)),
                             h2bits(__floats2half2_rn(x.z, x.w)));
        reinterpret_cast<uint2*>(g_entAH)[(size_t)w * 16 + l] = u;
        float2 h0 = f2up(hv.x), h1 = f2up(hv.y);
        float4 o = make_float4(h0.x + x.x, h0.y + x.y, h1.x + x.z, h1.y + x.w);
        reinterpret_cast<float4*>(out_ent)[(size_t)w * 16 + l] = o;
    }
}

// ---------------- kg1 device body ----------------
__device__ __forceinline__ void kg1_body(int blk, int t,
                                         float* __restrict__ out_ent,
                                         const ulonglong2* sW) {
    int w = blk * 8 + (t >> 5);
    int lane = t & 31, half = lane >> 4, l = lane & 15;
    int off = g_offE[w], deg = g_offE[w + 1] - off;

    ulonglong2 acc; acc.x = 0ULL; acc.y = 0ULL;
#pragma unroll 2
    for (int i = half; i < deg; i += 2) {
        int pk = __ldg(&g_pkE[off + i]);
        float m = __ldg(&g_mask[off + i]);
        int ty = pk >> 20;
        int tl = pk & 0xFFFFF;
        uint2 raw = __ldg(&reinterpret_cast<const uint2*>(g_entAH)[(size_t)tl * 16 + l]);
        ulonglong2 wv = sW[ty * 16 + l];
        u64 mp = f2bcast(m);
        acc.x = f2fma(f2mul(h2f2(raw.x), wv.x), mp, acc.x);
        acc.y = f2fma(f2mul(h2f2(raw.y), wv.y), mp, acc.y);
    }
    __syncwarp();
    float2 a0 = f2up(acc.x), a1 = f2up(acc.y);
    float4 a = make_float4(a0.x, a0.y, a1.x, a1.y);
    a.x += __shfl_xor_sync(0xffffffffu, a.x, 16);
    a.y += __shfl_xor_sync(0xffffffffu, a.y, 16);
    a.z += __shfl_xor_sync(0xffffffffu, a.z, 16);
    a.w += __shfl_xor_sync(0xffffffffu, a.w, 16);

    float ss = red16(dot4(a, a), 0xffffffffu);
    float inv = 1.f / fmaxf(sqrtf(ss), 1e-12f);
    if (half == 0) {
        float4 o = reinterpret_cast<const float4*>(out_ent)[(size_t)w * 16 + l];
        o.x += a.x * inv; o.y += a.y * inv;
        o.z += a.z * inv; o.w += a.w * inv;
        reinterpret_cast<float4*>(out_ent)[(size_t)w * 16 + l] = o;
    }
}

// ---------------- ui device body ----------------
template <int HOP>
__device__ __forceinline__ void ui_body(int blk, int t,
                                        const float* __restrict__ user_emb,
                                        float* __restrict__ out_usr,
                                        const float4* sL, const float4* sD) {
    int u = blk * 8 + (t >> 5);           // UIB*8 == N_USR exactly
    int lane = t & 31, half = lane >> 4, l = lane & 15;
    unsigned hm = 0xFFFFu << (half * 16);
    const float*  usr_src = (HOP == 0) ? user_emb : g_usrA;
    const __half* entH    = (HOP == 0) ? g_entH : g_entAH;

    float4 uv = __ldg(&reinterpret_cast<const float4*>(usr_src)[(size_t)u * 16 + l]);

    float d0 = red16(dot4(uv, sL[0 * 16 + l]), hm);
    float d1 = red16(dot4(uv, sL[1 * 16 + l]), hm);
    float d2 = red16(dot4(uv, sL[2 * 16 + l]), hm);
    float d3 = red16(dot4(uv, sL[3 * 16 + l]), hm);
    float m = fmaxf(fmaxf(d0, d1), fmaxf(d2, d3));
    d0 = __expf(d0 - m); d1 = __expf(d1 - m); d2 = __expf(d2 - m); d3 = __expf(d3 - m);
    float invs = 1.f / (d0 + d1 + d2 + d3);
    d0 *= invs; d1 *= invs; d2 *= invs; d3 *= invs;

    int off = g_offU[u], deg = g_offU[u + 1] - off;
    ulonglong2 acc; acc.x = 0ULL; acc.y = 0ULL;
#pragma unroll 2
    for (int i = half; i < deg; i += 2) {
        int2 p = __ldg(&g_uiP[off + i]);
        u64 vp = f2bcast(__int_as_float(p.y));
        uint2 raw = __ldg(&reinterpret_cast<const uint2*>(entH)[(size_t)p.x * 16 + l]);
        acc.x = f2fma(h2f2(raw.x), vp, acc.x);
        acc.y = f2fma(h2f2(raw.y), vp, acc.y);
    }
    __syncwarp();
    float2 c0 = f2up(acc.x), c1 = f2up(acc.y);
    float4 a = make_float4(c0.x, c0.y, c1.x, c1.y);
    a.x += __shfl_xor_sync(0xffffffffu, a.x, 16);
    a.y += __shfl_xor_sync(0xffffffffu, a.y, 16);
    a.z += __shfl_xor_sync(0xffffffffu, a.z, 16);
    a.w += __shfl_xor_sync(0xffffffffu, a.w, 16);

    float4 b0 = sD[0 * 16 + l], b1 = sD[1 * 16 + l], b2 = sD[2 * 16 + l], b3 = sD[3 * 16 + l];
    float4 mix;
    mix.x = 1.f + d0 * b0.x + d1 * b1.x + d2 * b2.x + d3 * b3.x;
    mix.y = 1.f + d0 * b0.y + d1 * b1.y + d2 * b2.y + d3 * b3.y;
    mix.z = 1.f + d0 * b0.z + d1 * b1.z + d2 * b2.z + d3 * b3.z;
    mix.w = 1.f + d0 * b0.w + d1 * b1.w + d2 * b2.w + d3 * b3.w;

    float4 x = make_float4(a.x * mix.x, a.y * mix.y, a.z * mix.z, a.w * mix.w);
    float ss = red16(dot4(x, x), 0xffffffffu);
    float inv = 1.f / fmaxf(sqrtf(ss), 1e-12f);
    x.x *= inv; x.y *= inv; x.z *= inv; x.w *= inv;

    if (half == 0) {
        if (HOP == 0) {
            reinterpret_cast<float4*>(g_usrA)[(size_t)u * 16 + l] = x;
            float4 o = make_float4(uv.x + x.x, uv.y + x.y, uv.z + x.z, uv.w + x.w);
            reinterpret_cast<float4*>(out_usr)[(size_t)u * 16 + l] = o;
        } else {
            float4 o = reinterpret_cast<const float4*>(out_usr)[(size_t)u * 16 + l];
            o.x += x.x; o.y += x.y; o.z += x.z; o.w += x.w;
            reinterpret_cast<float4*>(out_usr)[(size_t)u * 16 + l] = o;
        }
    }
}

// ---------------- fused hop kernels (8 CTAs/SM) ----------------
__global__ void __launch_bounds__(256, 8) k_fused0(const float* __restrict__ ent,
                                                   const float* __restrict__ usr,
                                                   const float* __restrict__ latent,
                                                   const float* __restrict__ weight,
                                                   float* __restrict__ out_ent,
                                                   float* __restrict__ out_usr) {
    __shared__ float4 sA[N_RELM1 * 16];
    __shared__ float4 sB[N_RELM1 * 16];
    __shared__ float  sWn[N_RELM1];
    int t = threadIdx.x;
    bool isKG = blockIdx.x < KGB;
    if (isKG) {
        for (int i = t; i < N_RELM1 * 16; i += 256)
            sB[i] = reinterpret_cast<const float4*>(weight)[i];
        if (t < N_RELM1) sWn[t] = g_wn2[t];
    } else {
        for (int i = t; i < N_FACT * 16; i += 256) {
            sA[i] = reinterpret_cast<const float4*>(latent)[i];
            sB[i] = reinterpret_cast<const float4*>(g_dw)[i];
        }
    }
    __syncthreads();
    if (isKG) kg0_body(blockIdx.x, t, ent, out_ent,
                       reinterpret_cast<const ulonglong2*>(sB), sWn);
    else      ui_body<0>(blockIdx.x - KGB, t, usr, out_usr, sA, sB);
}

__global__ void __launch_bounds__(256, 8) k_fused1(const float* __restrict__ usr,
                                                   const float* __restrict__ latent,
                                                   const float* __restrict__ weight,
                                                   float* __restrict__ out_ent,
                                                   float* __restrict__ out_usr) {
    __shared__ float4 sA[N_RELM1 * 16];
    __shared__ float4 sB[N_RELM1 * 16];
    int t = threadIdx.x;
    bool isKG = blockIdx.x < KGB;
    if (isKG) {
        for (int i = t; i < N_RELM1 * 16; i += 256)
            sB[i] = reinterpret_cast<const float4*>(weight)[i];
    } else {
        for (int i = t; i < N_FACT * 16; i += 256) {
            sA[i] = reinterpret_cast<const float4*>(latent)[i];
            sB[i] = reinterpret_cast<const float4*>(g_dw)[i];
        }
    }
    __syncthreads();
    if (isKG) kg1_body(blockIdx.x, t, out_ent,
                       reinterpret_cast<const ulonglong2*>(sB));
    else      ui_body<1>(blockIdx.x - KGB, t, usr, out_usr, sA, sB);
}

// ---------------- launch ----------------
extern "C" void kernel_launch(void* const* d_in, const int* in_sizes, int n_in,
                              void* d_out, int out_size) {
    const float* user_emb   = (const float*)d_in[0];
    const float* entity_emb = (const float*)d_in[1];
    const float* latent     = (const float*)d_in[2];
    const float* weight     = (const float*)d_in[3];
    const float* att        = (const float*)d_in[4];
    const float* kgW        = (const float*)d_in[5];
    const float* ui_vals    = (const float*)d_in[6];
    const int*   edge_index = (const int*)d_in[7];
    const int*   etype      = (const int*)d_in[8];
    const int*   ui_rows    = (const int*)d_in[9];
    const int*   ui_cols    = (const int*)d_in[10];

    const int* head = edge_index;
    const int* tail = edge_index + N_EDGE;

    float* out     = (float*)d_out;
    float* out_ent = out;
    float* out_usr = out + (size_t)N_ENT * C;
    float* out_cor = out + (size_t)N_ENT * C + (size_t)N_USR * C;

    const int TB = 256;

    k_count<<<EB + 1 + HB, TB>>>(head, ui_rows, weight, kgW, att, out_cor,
                                 entity_emb);                            // 1 (+prep+stage)
    k_scan<<<NB_E + NB_U + SBK, SCAN_B>>>(entity_emb);                   // 2 (+score table)
    k_fill<<<EB, TB>>>(head, tail, etype, ui_rows, ui_cols, ui_vals);    // 3 (+hist)
    k_fused0<<<KGB + UIB, TB>>>(entity_emb, user_emb, latent, weight,    // 4 (profiled)
                                out_ent, out_usr);
    k_fused1<<<KGB + UIB, TB>>>(user_emb, latent, weight,                // 5
                                out_ent, out_usr);
}